// round 1
// baseline (speedup 1.0000x reference)
#include <cuda_runtime.h>
#include <cuda_bf16.h>
#include <cstdint>

#define IN_F   4096
#define OUT_F  768
#define NB     8
#define BITS   (OUT_F * NB)   // 6144
#define BATCH  1024

// ---------------- device scratch (no allocations allowed) ----------------
__device__ float g_reg_sum;
__device__ float g_recon_sum;
__device__ __nv_bfloat16 g_wT[(size_t)OUT_F * IN_F];   // int_weights^T [768][4096] bf16
__device__ __nv_bfloat16 g_lat[(size_t)BATCH * IN_F];  // latent bf16   [1024][4096]
__device__ float g_t[(size_t)BATCH * OUT_F];           // int_sum/255   [1024][768]

__device__ __forceinline__ float tanh_fast(float x) {
    float y;
    asm("tanh.approx.f32 %0, %1;" : "=f"(y) : "f"(x));
    return y;
}

// ---------------- kernels ----------------
__global__ void k_init() {
    g_reg_sum = 0.f;
    g_recon_sum = 0.f;
}

// sigmoid(weight) -> reg partials + int_weights (transposed bf16 out)
// block: 32x32 tile of (k=in, n=out); 256 threads, 4 cells each.
__global__ void k_weights(const float* __restrict__ w) {
    __shared__ float s_iw[32][33];
    __shared__ float s_red[8];
    const float pw[8] = {1.f, 2.f, 4.f, 8.f, 16.f, 32.f, 64.f, -128.f};

    int k0 = blockIdx.x * 32;   // gridDim.x = 128
    int n0 = blockIdx.y * 32;   // gridDim.y = 24
    int t = threadIdx.x;

    float regloc = 0.f;
#pragma unroll
    for (int i = 0; i < 4; i++) {
        int c = t + i * 256;
        int kk = c >> 5, nn = c & 31;
        const float4* p = reinterpret_cast<const float4*>(
            w + (size_t)(k0 + kk) * BITS + (size_t)(n0 + nn) * 8);
        float4 w0 = p[0], w1 = p[1];
        float xs[8] = {w0.x, w0.y, w0.z, w0.w, w1.x, w1.y, w1.z, w1.w};
        float iw = 0.f;
#pragma unroll
        for (int b = 0; b < 8; b++) {
            float th = tanh_fast(0.5f * xs[b]);      // sigmoid = 0.5 + 0.5*th
            iw = fmaf(0.5f + 0.5f * th, pw[b], iw);
            regloc += 0.5f - 0.5f * fabsf(th);       // min(p, 1-p)
        }
        s_iw[kk][nn] = iw;
    }
    __syncthreads();
#pragma unroll
    for (int i = 0; i < 4; i++) {
        int c = t + i * 256;
        int nn = c >> 5, kk = c & 31;   // transposed write: coalesced along k
        g_wT[(size_t)(n0 + nn) * IN_F + (k0 + kk)] = __float2bfloat16(s_iw[kk][nn]);
    }
    // block-reduce reg partial
#pragma unroll
    for (int o = 16; o > 0; o >>= 1)
        regloc += __shfl_xor_sync(0xffffffffu, regloc, o);
    if ((t & 31) == 0) s_red[t >> 5] = regloc;
    __syncthreads();
    if (t == 0) {
        float s = 0.f;
#pragma unroll
        for (int i = 0; i < 8; i++) s += s_red[i];
        atomicAdd(&g_reg_sum, s);
    }
}

// int_sum / 255 for each (b, o)
__global__ void k_intsum(const float* __restrict__ ts) {
    int c = blockIdx.x * 256 + threadIdx.x;   // 0 .. 1024*768-1
    const float4* p = reinterpret_cast<const float4*>(ts + (size_t)c * 8);
    float4 a = p[0], b = p[1];
    float v = a.x + 2.f * a.y + 4.f * a.z + 8.f * a.w
            + 16.f * b.x + 32.f * b.y + 64.f * b.z - 128.f * b.w;
    g_t[c] = v * (1.0f / 255.0f);
}

// latent fp32 -> bf16
__global__ void k_convA(const float* __restrict__ lat) {
    int c = blockIdx.x * 256 + threadIdx.x;   // 1 float4 each
    float4 v = reinterpret_cast<const float4*>(lat)[c];
    __nv_bfloat162* o = reinterpret_cast<__nv_bfloat162*>(g_lat);
    o[2 * c]     = __floats2bfloat162_rn(v.x, v.y);
    o[2 * c + 1] = __floats2bfloat162_rn(v.z, v.w);
}

// GEMM (bf16 mma.sync 16x8x16) + fused squared-error reduction
// CTA tile 64x64, BK=32, 8 warps (2 M-stripes x 4 N-stripes), each warp 32x16.
#define BK  32
#define PAD 40   // padded smem row (bf16 elems) for conflict-free fragment loads

__global__ void k_gemm_loss() {
    __shared__ uint16_t As[64 * PAD];
    __shared__ uint16_t Bs[64 * PAD];
    __shared__ float s_red[8];

    int n0 = blockIdx.x * 64;   // gridDim.x = 12
    int m0 = blockIdx.y * 64;   // gridDim.y = 16
    int t = threadIdx.x;
    int wid = t >> 5, lane = t & 31;
    int wm = wid & 1, wn = wid >> 1;
    int gid = lane >> 2, tig = lane & 3;

    float acc[2][2][4] = {};

    int ldrow = t >> 2;           // 0..63
    int ldkg  = (t & 3) * 8;      // 0,8,16,24
    const uint4* gA = reinterpret_cast<const uint4*>(
        g_lat + (size_t)(m0 + ldrow) * IN_F + ldkg);
    const uint4* gB = reinterpret_cast<const uint4*>(
        g_wT + (size_t)(n0 + ldrow) * IN_F + ldkg);
    uint4* sA = reinterpret_cast<uint4*>(&As[ldrow * PAD + ldkg]);
    uint4* sB = reinterpret_cast<uint4*>(&Bs[ldrow * PAD + ldkg]);

    for (int kc = 0; kc < IN_F / BK; kc++) {
        uint4 va = gA[kc * (BK / 8)];
        uint4 vb = gB[kc * (BK / 8)];
        __syncthreads();            // previous chunk consumed
        *sA = va;
        *sB = vb;
        __syncthreads();

#pragma unroll
        for (int s = 0; s < 2; s++) {
            int ks = s * 16;
            uint32_t afr[2][4], bfr[2][2];
#pragma unroll
            for (int mt = 0; mt < 2; mt++) {
                int r = wm * 32 + mt * 16 + gid;
                afr[mt][0] = *reinterpret_cast<const uint32_t*>(&As[r * PAD + ks + tig * 2]);
                afr[mt][1] = *reinterpret_cast<const uint32_t*>(&As[(r + 8) * PAD + ks + tig * 2]);
                afr[mt][2] = *reinterpret_cast<const uint32_t*>(&As[r * PAD + ks + tig * 2 + 8]);
                afr[mt][3] = *reinterpret_cast<const uint32_t*>(&As[(r + 8) * PAD + ks + tig * 2 + 8]);
            }
#pragma unroll
            for (int nt = 0; nt < 2; nt++) {
                int nc = wn * 16 + nt * 8 + gid;
                bfr[nt][0] = *reinterpret_cast<const uint32_t*>(&Bs[nc * PAD + ks + tig * 2]);
                bfr[nt][1] = *reinterpret_cast<const uint32_t*>(&Bs[nc * PAD + ks + tig * 2 + 8]);
            }
#pragma unroll
            for (int mt = 0; mt < 2; mt++)
#pragma unroll
                for (int nt = 0; nt < 2; nt++) {
                    asm volatile(
                        "mma.sync.aligned.m16n8k16.row.col.f32.bf16.bf16.f32 "
                        "{%0,%1,%2,%3}, {%4,%5,%6,%7}, {%8,%9}, {%0,%1,%2,%3};"
                        : "+f"(acc[mt][nt][0]), "+f"(acc[mt][nt][1]),
                          "+f"(acc[mt][nt][2]), "+f"(acc[mt][nt][3])
                        : "r"(afr[mt][0]), "r"(afr[mt][1]),
                          "r"(afr[mt][2]), "r"(afr[mt][3]),
                          "r"(bfr[nt][0]), "r"(bfr[nt][1]));
                }
        }
    }

    // fused loss: (pred/255 - t)^2
    float lsum = 0.f;
#pragma unroll
    for (int mt = 0; mt < 2; mt++)
#pragma unroll
        for (int nt = 0; nt < 2; nt++) {
            int r = m0 + wm * 32 + mt * 16 + gid;
            int nc = n0 + wn * 16 + nt * 8 + tig * 2;
            float2 t0 = *reinterpret_cast<const float2*>(&g_t[(size_t)r * OUT_F + nc]);
            float2 t1 = *reinterpret_cast<const float2*>(&g_t[(size_t)(r + 8) * OUT_F + nc]);
            float e0 = fmaf(acc[mt][nt][0], 1.f / 255.f, -t0.x);
            float e1 = fmaf(acc[mt][nt][1], 1.f / 255.f, -t0.y);
            float e2 = fmaf(acc[mt][nt][2], 1.f / 255.f, -t1.x);
            float e3 = fmaf(acc[mt][nt][3], 1.f / 255.f, -t1.y);
            lsum += e0 * e0 + e1 * e1 + e2 * e2 + e3 * e3;
        }
#pragma unroll
    for (int o = 16; o > 0; o >>= 1)
        lsum += __shfl_xor_sync(0xffffffffu, lsum, o);
    if (lane == 0) s_red[wid] = lsum;
    __syncthreads();
    if (t == 0) {
        float s = 0.f;
#pragma unroll
        for (int i = 0; i < 8; i++) s += s_red[i];
        atomicAdd(&g_recon_sum, s);
    }
}

__global__ void k_final(float* __restrict__ out, int out_size) {
    float recon = g_recon_sum * (1.0f / ((float)BATCH * OUT_F));
    float reg   = 0.001f * g_reg_sum * (1.0f / ((float)IN_F * (float)BITS));
    if (out_size > 0) out[0] = recon + reg;
    if (out_size > 1) out[1] = recon;
    if (out_size > 2) out[2] = reg;
}

// ---------------- launch ----------------
extern "C" void kernel_launch(void* const* d_in, const int* in_sizes, int n_in,
                              void* d_out, int out_size) {
    const float* latent   = (const float*)d_in[0];
    const float* true_sum = (const float*)d_in[1];
    const float* weight   = (const float*)d_in[2];

    k_init<<<1, 1>>>();
    k_weights<<<dim3(IN_F / 32, OUT_F / 32), 256>>>(weight);
    k_intsum<<<(BATCH * OUT_F) / 256, 256>>>(true_sum);
    k_convA<<<(BATCH * IN_F / 4) / 256, 256>>>(latent);
    k_gemm_loss<<<dim3(OUT_F / 64, BATCH / 64), 256>>>();
    k_final<<<1, 1>>>((float*)d_out, out_size);
}

// round 2
// speedup vs baseline: 1.5642x; 1.5642x over previous
#include <cuda_runtime.h>
#include <cuda_bf16.h>
#include <cstdint>

#define IN_F   4096
#define OUT_F  768
#define NB     8
#define BITS   (OUT_F * NB)   // 6144
#define BATCH  1024

#define BM 64
#define BN 64
#define BKK 64

// ---------------- device scratch (no allocations allowed) ----------------
__device__ __nv_bfloat16 g_wT[(size_t)OUT_F * IN_F];   // int_weights^T [768][4096] bf16
__device__ __nv_bfloat16 g_lat[(size_t)BATCH * IN_F];  // latent bf16   [1024][4096]
__device__ float g_reg_part[3072];                     // per-CTA reg partials
__device__ float g_recon_part[192];                    // per-CTA recon partials

__device__ __forceinline__ float tanh_fast(float x) {
    float y;
    asm("tanh.approx.f32 %0, %1;" : "=f"(y) : "f"(x));
    return y;
}
__device__ __forceinline__ uint32_t cvta_s(const void* p) {
    return (uint32_t)__cvta_generic_to_shared(p);
}
#define CP_ASYNC16(s, g) asm volatile("cp.async.cg.shared.global [%0], [%1], 16;\n" :: "r"(s), "l"(g))
#define CP_COMMIT        asm volatile("cp.async.commit_group;\n" ::: "memory")
#define CP_WAIT0         asm volatile("cp.async.wait_group 0;\n" ::: "memory")
#define CP_WAIT1         asm volatile("cp.async.wait_group 1;\n" ::: "memory")
#define LDSM4(r0, r1, r2, r3, a) \
    asm volatile("ldmatrix.sync.aligned.m8n8.x4.shared.b16 {%0,%1,%2,%3}, [%4];\n" \
                 : "=r"(r0), "=r"(r1), "=r"(r2), "=r"(r3) : "r"(a))
#define MMA(d, a, b0, b1) \
    asm volatile("mma.sync.aligned.m16n8k16.row.col.f32.bf16.bf16.f32 " \
                 "{%0,%1,%2,%3},{%4,%5,%6,%7},{%8,%9},{%0,%1,%2,%3};\n" \
                 : "+f"(d[0]), "+f"(d[1]), "+f"(d[2]), "+f"(d[3]) \
                 : "r"(a[0]), "r"(a[1]), "r"(a[2]), "r"(a[3]), "r"(b0), "r"(b1))

// ---------------- kernels ----------------

// sigmoid(weight) -> reg partials + int_weights (transposed bf16 out)
__global__ void k_weights(const float* __restrict__ w) {
    __shared__ float s_iw[32][33];
    __shared__ float s_red[8];
    const float pw[8] = {1.f, 2.f, 4.f, 8.f, 16.f, 32.f, 64.f, -128.f};

    int k0 = blockIdx.x * 32;   // gridDim.x = 128
    int n0 = blockIdx.y * 32;   // gridDim.y = 24
    int t = threadIdx.x;

    float regloc = 0.f;
#pragma unroll
    for (int i = 0; i < 4; i++) {
        int c = t + i * 256;
        int kk = c >> 5, nn = c & 31;
        const float4* p = reinterpret_cast<const float4*>(
            w + (size_t)(k0 + kk) * BITS + (size_t)(n0 + nn) * 8);
        float4 w0 = p[0], w1 = p[1];
        float xs[8] = {w0.x, w0.y, w0.z, w0.w, w1.x, w1.y, w1.z, w1.w};
        float iw = 0.f;
#pragma unroll
        for (int b = 0; b < 8; b++) {
            float th = tanh_fast(0.5f * xs[b]);      // sigmoid = 0.5 + 0.5*th
            iw = fmaf(0.5f + 0.5f * th, pw[b], iw);
            regloc += 0.5f - 0.5f * fabsf(th);       // min(p, 1-p)
        }
        s_iw[kk][nn] = iw;
    }
    __syncthreads();
#pragma unroll
    for (int i = 0; i < 4; i++) {
        int c = t + i * 256;
        int nn = c >> 5, kk = c & 31;   // transposed write: coalesced along k
        g_wT[(size_t)(n0 + nn) * IN_F + (k0 + kk)] = __float2bfloat16(s_iw[kk][nn]);
    }
#pragma unroll
    for (int o = 16; o > 0; o >>= 1)
        regloc += __shfl_xor_sync(0xffffffffu, regloc, o);
    if ((t & 31) == 0) s_red[t >> 5] = regloc;
    __syncthreads();
    if (t == 0) {
        float s = 0.f;
#pragma unroll
        for (int i = 0; i < 8; i++) s += s_red[i];
        g_reg_part[blockIdx.y * 128 + blockIdx.x] = s;
    }
}

// latent fp32 -> bf16, 4 float4 per thread (MLP=4)
__global__ void k_convA(const float* __restrict__ lat) {
    int i = blockIdx.x * blockDim.x + threadIdx.x;
    int stride = gridDim.x * blockDim.x;   // 262144
    const float4* src = reinterpret_cast<const float4*>(lat);
    __nv_bfloat162* o = reinterpret_cast<__nv_bfloat162*>(g_lat);
    float4 v[4];
#pragma unroll
    for (int j = 0; j < 4; j++) v[j] = src[i + j * stride];
#pragma unroll
    for (int j = 0; j < 4; j++) {
        int idx = i + j * stride;
        o[2 * idx]     = __floats2bfloat162_rn(v[j].x, v[j].y);
        o[2 * idx + 1] = __floats2bfloat162_rn(v[j].z, v[j].w);
    }
}

// int_sum(r, n) / 255 computed on the fly from true_sum
__device__ __forceinline__ float tval(const float* __restrict__ ts, int r, int n) {
    const float4* p = reinterpret_cast<const float4*>(ts + ((size_t)r * OUT_F + n) * 8);
    float4 a = p[0], b = p[1];
    return (a.x + 2.f * a.y + 4.f * a.z + 8.f * a.w
            + 16.f * b.x + 32.f * b.y + 64.f * b.z - 128.f * b.w) * (1.0f / 255.0f);
}

// tile loader: 2 A-chunks + 2 B-chunks of 16B per thread, XOR-swizzled smem
__device__ __forceinline__ void load_tile(
    uint16_t* As, uint16_t* Bs,
    const __nv_bfloat16* gA, const __nv_bfloat16* gB,
    int kbase, int row0, int chunk0)
{
    int sw = (chunk0 ^ (row0 & 7)) << 3;            // same for row0 and row0+32
    CP_ASYNC16(cvta_s(&As[row0 * BKK + sw]),
               gA + (size_t)row0 * IN_F + kbase + chunk0 * 8);
    CP_ASYNC16(cvta_s(&As[(row0 + 32) * BKK + sw]),
               gA + (size_t)(row0 + 32) * IN_F + kbase + chunk0 * 8);
    CP_ASYNC16(cvta_s(&Bs[row0 * BKK + sw]),
               gB + (size_t)row0 * IN_F + kbase + chunk0 * 8);
    CP_ASYNC16(cvta_s(&Bs[(row0 + 32) * BKK + sw]),
               gB + (size_t)(row0 + 32) * IN_F + kbase + chunk0 * 8);
}

// GEMM (ldmatrix + mma.sync bf16, double-buffered cp.async) + fused loss
__global__ void k_gemm_loss(const float* __restrict__ ts) {
    __shared__ __align__(16) uint16_t As[2][BM * BKK];
    __shared__ __align__(16) uint16_t Bs[2][BN * BKK];
    __shared__ float s_red[8];

    int n0 = blockIdx.x * BN;   // gridDim.x = 12
    int m0 = blockIdx.y * BM;   // gridDim.y = 16
    int t = threadIdx.x;
    int wid = t >> 5, lane = t & 31;
    int wm = wid & 1, wn = wid >> 1;

    int row0 = t >> 3, chunk0 = t & 7;

    const __nv_bfloat16* gA = g_lat + (size_t)m0 * IN_F;
    const __nv_bfloat16* gB = g_wT + (size_t)n0 * IN_F;

    float acc[2][2][4] = {};

    // precompute ldmatrix lane addresses (row, kchunk-part)
    int rA0 = wm * 32 + (lane & 15);
    int rA1 = rA0 + 16;
    int kA  = lane >> 4;                               // 0/1 -> +0/+8 k
    int rB  = wn * 16 + ((lane >> 4) << 3) + (lane & 7);
    int kB  = (lane >> 3) & 1;

    load_tile(As[0], Bs[0], gA, gB, 0, row0, chunk0);
    CP_COMMIT;

    int buf = 0;
    const int NKC = IN_F / BKK;   // 64
    for (int kc = 0; kc < NKC; kc++) {
        if (kc + 1 < NKC) {
            load_tile(As[buf ^ 1], Bs[buf ^ 1], gA, gB, (kc + 1) * BKK, row0, chunk0);
            CP_COMMIT;
            CP_WAIT1;
        } else {
            CP_WAIT0;
        }
        __syncthreads();

        const uint16_t* Ab = As[buf];
        const uint16_t* Bb = Bs[buf];
#pragma unroll
        for (int kc8 = 0; kc8 < 8; kc8 += 2) {      // ks = kc8*8: 0,16,32,48
            uint32_t a0[4], a1[4], b[4];
            int ka = kc8 + kA;
            int kb = kc8 + kB;
            LDSM4(a0[0], a0[1], a0[2], a0[3],
                  cvta_s(&Ab[rA0 * BKK + ((ka ^ (rA0 & 7)) << 3)]));
            LDSM4(a1[0], a1[1], a1[2], a1[3],
                  cvta_s(&Ab[rA1 * BKK + ((ka ^ (rA1 & 7)) << 3)]));
            LDSM4(b[0], b[1], b[2], b[3],
                  cvta_s(&Bb[rB * BKK + ((kb ^ (rB & 7)) << 3)]));
            MMA(acc[0][0], a0, b[0], b[1]);
            MMA(acc[0][1], a0, b[2], b[3]);
            MMA(acc[1][0], a1, b[0], b[1]);
            MMA(acc[1][1], a1, b[2], b[3]);
        }
        __syncthreads();
        buf ^= 1;
    }

    // fused loss: (pred/255 - int_sum/255)^2, int_sum computed from true_sum
    int gid = lane >> 2, tig = lane & 3;
    float lsum = 0.f;
#pragma unroll
    for (int mt = 0; mt < 2; mt++)
#pragma unroll
        for (int nt = 0; nt < 2; nt++) {
            int r  = m0 + wm * 32 + mt * 16 + gid;
            int nc = n0 + wn * 16 + nt * 8 + tig * 2;
            float t00 = tval(ts, r,     nc);
            float t01 = tval(ts, r,     nc + 1);
            float t10 = tval(ts, r + 8, nc);
            float t11 = tval(ts, r + 8, nc + 1);
            float e0 = fmaf(acc[mt][nt][0], 1.f / 255.f, -t00);
            float e1 = fmaf(acc[mt][nt][1], 1.f / 255.f, -t01);
            float e2 = fmaf(acc[mt][nt][2], 1.f / 255.f, -t10);
            float e3 = fmaf(acc[mt][nt][3], 1.f / 255.f, -t11);
            lsum += e0 * e0 + e1 * e1 + e2 * e2 + e3 * e3;
        }
#pragma unroll
    for (int o = 16; o > 0; o >>= 1)
        lsum += __shfl_xor_sync(0xffffffffu, lsum, o);
    if (lane == 0) s_red[wid] = lsum;
    __syncthreads();
    if (t == 0) {
        float s = 0.f;
#pragma unroll
        for (int i = 0; i < 8; i++) s += s_red[i];
        g_recon_part[blockIdx.y * 12 + blockIdx.x] = s;
    }
}

__global__ void k_final(float* __restrict__ out, int out_size) {
    __shared__ float sr[8], ss[8];
    int t = threadIdx.x;
    float r = 0.f, s = 0.f;
    for (int i = t; i < 3072; i += 256) r += g_reg_part[i];
    if (t < 192) s = g_recon_part[t];
#pragma unroll
    for (int o = 16; o > 0; o >>= 1) {
        r += __shfl_xor_sync(0xffffffffu, r, o);
        s += __shfl_xor_sync(0xffffffffu, s, o);
    }
    if ((t & 31) == 0) { sr[t >> 5] = r; ss[t >> 5] = s; }
    __syncthreads();
    if (t == 0) {
        float R = 0.f, S = 0.f;
#pragma unroll
        for (int i = 0; i < 8; i++) { R += sr[i]; S += ss[i]; }
        float recon = S * (1.0f / ((float)BATCH * OUT_F));
        float reg   = 0.001f * R * (1.0f / ((float)IN_F * (float)BITS));
        if (out_size > 0) out[0] = recon + reg;
        if (out_size > 1) out[1] = recon;
        if (out_size > 2) out[2] = reg;
    }
}

// ---------------- launch ----------------
extern "C" void kernel_launch(void* const* d_in, const int* in_sizes, int n_in,
                              void* d_out, int out_size) {
    const float* latent   = (const float*)d_in[0];
    const float* true_sum = (const float*)d_in[1];
    const float* weight   = (const float*)d_in[2];

    k_weights<<<dim3(IN_F / 32, OUT_F / 32), 256>>>(weight);
    k_convA<<<(BATCH * IN_F / 4) / (256 * 4), 256>>>(latent);
    k_gemm_loss<<<dim3(OUT_F / BN, BATCH / BM), 256>>>(true_sum);
    k_final<<<1, 256>>>((float*)d_out, out_size);
}